// round 4
// baseline (speedup 1.0000x reference)
#include <cuda_runtime.h>

// EdgeNetwork fused kernel for GB300 (sm_103a)
//
// Strategy:
//  1) precompute_kernel: P1[n] = b1 + NF[n] @ W1[0:64], P2[n] = NF[n] @ W1[64:128]
//     into __device__ scratch (25.6MB, L2-resident).
//  2) edge_kernel: warp processes 8 edges; gather P1[src]+P2[dst], add ea@W1c
//     (16x64 mini-GEMM from smem), LN+leaky, 64x64 GEMM vs smem W2 with
//     8-edge register blocking and f32x2 packed FMAs, LN+leaky, dot with W3.
//
// NOTE: edge_index is int32 on device (JAX demotes int64 without x64 mode).

typedef unsigned long long u64;

#define DEVINL __device__ __forceinline__
#define FULLM 0xffffffffu

DEVINL u64 f2pack(float x, float y) {
    u64 d; asm("mov.b64 %0, {%1, %2};" : "=l"(d) : "f"(x), "f"(y)); return d;
}
DEVINL void f2unpack(u64 d, float &x, float &y) {
    asm("mov.b64 {%0, %1}, %2;" : "=f"(x), "=f"(y) : "l"(d));
}
DEVINL u64 f2fma(u64 a, u64 b, u64 c) {
    u64 d; asm("fma.rn.f32x2 %0, %1, %2, %3;" : "=l"(d) : "l"(a), "l"(b), "l"(c)); return d;
}
DEVINL u64 f2add(u64 a, u64 b) {
    u64 d; asm("add.rn.f32x2 %0, %1, %2;" : "=l"(d) : "l"(a), "l"(b)); return d;
}
DEVINL u64 f2dup(float x) { return f2pack(x, x); }

#define MAXN 50000
__device__ float g_P1[MAXN * 64];
__device__ float g_P2[MAXN * 64];

// ---------------------------------------------------------------------------
// Kernel 1: per-node precompute.  P1 = b1 + NF @ W1a, P2 = NF @ W1b
// ---------------------------------------------------------------------------
__global__ __launch_bounds__(256) void precompute_kernel(
    const float* __restrict__ NF, const float* __restrict__ W1,
    const float* __restrict__ b1, int n_nodes)
{
    __shared__ __align__(16) float sWa[4096];   // W1 rows 0..63   [k][c]
    __shared__ __align__(16) float sWb[4096];   // W1 rows 64..127 [k][c]
    __shared__ __align__(16) float sNF[8][68];  // per-warp node row (padded)

    int tid = threadIdx.x;
    for (int i = tid; i < 1024; i += 256) {
        ((float4*)sWa)[i] = ((const float4*)W1)[i];
        ((float4*)sWb)[i] = ((const float4*)(W1 + 4096))[i];
    }
    __syncthreads();

    int l = tid & 31, w = tid >> 5;
    int gw = blockIdx.x * 8 + w;
    int totW = gridDim.x * 8;
    u64 b1p = f2pack(b1[2 * l], b1[2 * l + 1]);

    const u64* wa = (const u64*)sWa;
    const u64* wb = (const u64*)sWb;

    for (int n = gw; n < n_nodes && n < MAXN; n += totW) {
        float2 v = ((const float2*)(NF + (size_t)n * 64))[l];
        sNF[w][2 * l] = v.x; sNF[w][2 * l + 1] = v.y;
        __syncwarp();

        u64 acc1 = b1p, acc2 = 0ull;
        #pragma unroll
        for (int k4 = 0; k4 < 16; k4++) {
            float4 x = ((const float4*)sNF[w])[k4];
            int k = 4 * k4;
            u64 x0 = f2dup(x.x), x1 = f2dup(x.y), x2 = f2dup(x.z), x3 = f2dup(x.w);
            acc1 = f2fma(x0, wa[(k + 0) * 32 + l], acc1);
            acc2 = f2fma(x0, wb[(k + 0) * 32 + l], acc2);
            acc1 = f2fma(x1, wa[(k + 1) * 32 + l], acc1);
            acc2 = f2fma(x1, wb[(k + 1) * 32 + l], acc2);
            acc1 = f2fma(x2, wa[(k + 2) * 32 + l], acc1);
            acc2 = f2fma(x2, wb[(k + 2) * 32 + l], acc2);
            acc1 = f2fma(x3, wa[(k + 3) * 32 + l], acc1);
            acc2 = f2fma(x3, wb[(k + 3) * 32 + l], acc2);
        }
        ((u64*)(g_P1 + ((size_t)n << 6)))[l] = acc1;
        ((u64*)(g_P2 + ((size_t)n << 6)))[l] = acc2;
        __syncwarp();   // protect sNF overwrite on next iteration
    }
}

// ---------------------------------------------------------------------------
// Kernel 2: per-edge fused MLP. One warp = 8 edges. Lane l owns cols 2l,2l+1.
// ---------------------------------------------------------------------------
__global__ __launch_bounds__(128, 4) void edge_kernel(
    const int* __restrict__ EI, const float* __restrict__ EA,
    const float* __restrict__ W1, const float* __restrict__ W2,
    const float* __restrict__ g1, const float* __restrict__ be1,
    const float* __restrict__ b2, const float* __restrict__ g2,
    const float* __restrict__ be2, const float* __restrict__ W3,
    const float* __restrict__ b3, float* __restrict__ OUT, int E)
{
    __shared__ __align__(16) float sW2f[4096];   // W2 [k][c]
    __shared__ __align__(16) float sW1cf[1024];  // W1 rows 128..143 [k][c]
    __shared__ __align__(16) float sG1[64], sBe1[64], sB2[64], sG2[64], sBe2[64], sW3f[64];
    __shared__ float sB3;
    // duplicated-value staging: [warp][k][t] holds {v,v}; row padded to 10 for banks
    __shared__ __align__(16) u64 sXD[4][64][10];
    __shared__ __align__(16) u64 sEAD[4][16][10];

    int tid = threadIdx.x;
    for (int i = tid; i < 1024; i += 128) ((float4*)sW2f)[i] = ((const float4*)W2)[i];
    for (int i = tid; i < 256; i += 128)
        ((float4*)sW1cf)[i] = ((const float4*)(W1 + 8192))[i];
    if (tid < 64) {
        sG1[tid] = g1[tid]; sBe1[tid] = be1[tid]; sB2[tid] = b2[tid];
        sG2[tid] = g2[tid]; sBe2[tid] = be2[tid]; sW3f[tid] = W3[tid];
    }
    if (tid == 0) sB3 = b3[0];
    __syncthreads();

    int l = tid & 31, w = tid >> 5;
    int gw = blockIdx.x * 4 + w, totW = gridDim.x * 4;
    int nG = (E + 7) >> 3;

    float2 g1v  = ((const float2*)sG1)[l];
    float2 be1v = ((const float2*)sBe1)[l];
    float2 g2v  = ((const float2*)sG2)[l];
    float2 be2v = ((const float2*)sBe2)[l];
    float2 w3v  = ((const float2*)sW3f)[l];
    u64 b2p = ((const u64*)sB2)[l];
    float bias3 = sB3;
    const u64* w1c = (const u64*)sW1cf;
    const u64* w2p = (const u64*)sW2f;

    for (int g = gw; g < nG; g += totW) {
        int e0 = g << 3;

        // ---- load edge indices (lanes 0-7: src t, lanes 8-15: dst t) ----
        int idx = 0;
        if (l < 16) {
            int col = min(e0 + (l & 7), E - 1);
            idx = EI[(size_t)(l >> 3) * (size_t)E + (size_t)col];
        }

        // ---- gather P1[src] + P2[dst] ----
        u64 acc[8];
        #pragma unroll
        for (int t = 0; t < 8; t++) {
            int s = __shfl_sync(FULLM, idx, t);
            int d = __shfl_sync(FULLM, idx, 8 + t);
            u64 a = *(const u64*)(g_P1 + ((size_t)s << 6) + 2 * l);
            u64 b = *(const u64*)(g_P2 + ((size_t)d << 6) + 2 * l);
            acc[t] = f2add(a, b);
        }

        // ---- stage edge_attr (duplicated) ----
        {
            int t = l >> 2, k0 = (l & 3) << 2;
            int e = min(e0 + t, E - 1);
            float4 ev = *(const float4*)(EA + ((size_t)e << 4) + k0);
            sEAD[w][k0 + 0][t] = f2dup(ev.x);
            sEAD[w][k0 + 1][t] = f2dup(ev.y);
            sEAD[w][k0 + 2][t] = f2dup(ev.z);
            sEAD[w][k0 + 3][t] = f2dup(ev.w);
        }
        __syncwarp();

        // ---- ea @ W1c  (16 x 64) ----
        #pragma unroll
        for (int k = 0; k < 16; k++) {
            u64 wv = w1c[k * 32 + l];
            const ulonglong2* xp = (const ulonglong2*)&sEAD[w][k][0];
            ulonglong2 q0 = xp[0], q1 = xp[1], q2 = xp[2], q3 = xp[3];
            acc[0] = f2fma(q0.x, wv, acc[0]);
            acc[1] = f2fma(q0.y, wv, acc[1]);
            acc[2] = f2fma(q1.x, wv, acc[2]);
            acc[3] = f2fma(q1.y, wv, acc[3]);
            acc[4] = f2fma(q2.x, wv, acc[4]);
            acc[5] = f2fma(q2.y, wv, acc[5]);
            acc[6] = f2fma(q3.x, wv, acc[6]);
            acc[7] = f2fma(q3.y, wv, acc[7]);
        }

        // ---- LayerNorm 1 + leaky ----
        float hx[8], hy[8], sums[8], sqs[8];
        #pragma unroll
        for (int t = 0; t < 8; t++) {
            float x, y; f2unpack(acc[t], x, y);
            hx[t] = x; hy[t] = y;
            sums[t] = x + y;
            sqs[t] = x * x + y * y;
        }
        #pragma unroll
        for (int r = 0; r < 5; r++) {
            int o = 16 >> r;
            #pragma unroll
            for (int t = 0; t < 8; t++) {
                sums[t] += __shfl_xor_sync(FULLM, sums[t], o);
                sqs[t]  += __shfl_xor_sync(FULLM, sqs[t], o);
            }
        }
        #pragma unroll
        for (int t = 0; t < 8; t++) {
            float mean = sums[t] * 0.015625f;
            float var  = fmaf(sqs[t], 0.015625f, -mean * mean);
            float rstd = rsqrtf(var + 1e-5f);
            float h0 = fmaf(hx[t] - mean, rstd * g1v.x, be1v.x);
            float h1 = fmaf(hy[t] - mean, rstd * g1v.y, be1v.y);
            hx[t] = fmaxf(h0, 0.1f * h0);
            hy[t] = fmaxf(h1, 0.1f * h1);
        }

        __syncwarp();   // all lanes done reading sXD from previous iteration
        {
            ulonglong2* r0 = (ulonglong2*)&sXD[w][2 * l][0];
            ulonglong2* r1 = (ulonglong2*)&sXD[w][2 * l + 1][0];
            r0[0] = make_ulonglong2(f2dup(hx[0]), f2dup(hx[1]));
            r0[1] = make_ulonglong2(f2dup(hx[2]), f2dup(hx[3]));
            r0[2] = make_ulonglong2(f2dup(hx[4]), f2dup(hx[5]));
            r0[3] = make_ulonglong2(f2dup(hx[6]), f2dup(hx[7]));
            r1[0] = make_ulonglong2(f2dup(hy[0]), f2dup(hy[1]));
            r1[1] = make_ulonglong2(f2dup(hy[2]), f2dup(hy[3]));
            r1[2] = make_ulonglong2(f2dup(hy[4]), f2dup(hy[5]));
            r1[3] = make_ulonglong2(f2dup(hy[6]), f2dup(hy[7]));
        }
        __syncwarp();

        // ---- h1 @ W2  (64 x 64) ----
        u64 acc2[8];
        #pragma unroll
        for (int t = 0; t < 8; t++) acc2[t] = b2p;
        #pragma unroll 8
        for (int k = 0; k < 64; k++) {
            u64 wv = w2p[k * 32 + l];
            const ulonglong2* xp = (const ulonglong2*)&sXD[w][k][0];
            ulonglong2 q0 = xp[0], q1 = xp[1], q2 = xp[2], q3 = xp[3];
            acc2[0] = f2fma(q0.x, wv, acc2[0]);
            acc2[1] = f2fma(q0.y, wv, acc2[1]);
            acc2[2] = f2fma(q1.x, wv, acc2[2]);
            acc2[3] = f2fma(q1.y, wv, acc2[3]);
            acc2[4] = f2fma(q2.x, wv, acc2[4]);
            acc2[5] = f2fma(q2.y, wv, acc2[5]);
            acc2[6] = f2fma(q3.x, wv, acc2[6]);
            acc2[7] = f2fma(q3.y, wv, acc2[7]);
        }

        // ---- LayerNorm 2 + leaky + dot(W3) ----
        #pragma unroll
        for (int t = 0; t < 8; t++) {
            float x, y; f2unpack(acc2[t], x, y);
            hx[t] = x; hy[t] = y;
            sums[t] = x + y;
            sqs[t] = x * x + y * y;
        }
        #pragma unroll
        for (int r = 0; r < 5; r++) {
            int o = 16 >> r;
            #pragma unroll
            for (int t = 0; t < 8; t++) {
                sums[t] += __shfl_xor_sync(FULLM, sums[t], o);
                sqs[t]  += __shfl_xor_sync(FULLM, sqs[t], o);
            }
        }
        float px[8];
        #pragma unroll
        for (int t = 0; t < 8; t++) {
            float mean = sums[t] * 0.015625f;
            float var  = fmaf(sqs[t], 0.015625f, -mean * mean);
            float rstd = rsqrtf(var + 1e-5f);
            float h0 = fmaf(hx[t] - mean, rstd * g2v.x, be2v.x);
            float h1 = fmaf(hy[t] - mean, rstd * g2v.y, be2v.y);
            h0 = fmaxf(h0, 0.1f * h0);
            h1 = fmaxf(h1, 0.1f * h1);
            px[t] = fmaf(h0, w3v.x, h1 * w3v.y);
        }
        #pragma unroll
        for (int r = 0; r < 5; r++) {
            int o = 16 >> r;
            #pragma unroll
            for (int t = 0; t < 8; t++)
                px[t] += __shfl_xor_sync(FULLM, px[t], o);
        }
        float ov = px[0];
        #pragma unroll
        for (int t = 1; t < 8; t++) ov = (l == t) ? px[t] : ov;
        if (l < 8) {
            int e = e0 + l;
            if (e < E) OUT[e] = ov + bias3;
        }
    }
}

// ---------------------------------------------------------------------------
// Launch
// ---------------------------------------------------------------------------
extern "C" void kernel_launch(void* const* d_in, const int* in_sizes, int n_in,
                              void* d_out, int out_size)
{
    const float* NF  = (const float*)d_in[0];      // (N, 64)
    const int*   EI  = (const int*)d_in[1];        // (2, E) int32 on device
    const float* EA  = (const float*)d_in[2];      // (E, 16)
    const float* W1  = (const float*)d_in[3];      // (144, 64)
    const float* b1  = (const float*)d_in[4];
    const float* g1  = (const float*)d_in[5];
    const float* be1 = (const float*)d_in[6];
    const float* W2  = (const float*)d_in[7];      // (64, 64)
    const float* b2  = (const float*)d_in[8];
    const float* g2  = (const float*)d_in[9];
    const float* be2 = (const float*)d_in[10];
    const float* W3  = (const float*)d_in[11];     // (64, 1)
    const float* b3  = (const float*)d_in[12];
    float* OUT = (float*)d_out;

    int n_nodes = in_sizes[0] / 64;
    int E       = in_sizes[1] / 2;
    if (E <= 0) return;

    precompute_kernel<<<592, 256>>>(NF, W1, b1, n_nodes);
    edge_kernel<<<592, 128>>>(EI, EA, W1, W2, g1, be1, b2, g2, be2, W3, b3, OUT, E);
}